// round 5
// baseline (speedup 1.0000x reference)
#include <cuda_runtime.h>
#include <cstdint>

// spspmm via counting-sort by target row; hot gather = one WARP per output row:
//   lanes split 4 pair-slots x 8 feature-slots -> ~95% of rows need a single
//   parallel iteration (Poisson(2) segment lengths), shfl_xor reduce, one
//   coalesced 128B store. No atomics on output, no zero-fill, no RMW read.

#define TAR_CAP 2100000
#define M_CAP   4200000
#define SCAN_T  1024
#define SCAN_I  4
#define SCAN_CHUNK (SCAN_T * SCAN_I)   // 4096

__device__ int  g_count[TAR_CAP];
__device__ int  g_offset[TAR_CAP];
__device__ int  g_cursor[TAR_CAP];
__device__ int2 g_cd[M_CAP];
__device__ int  g_blocksums[1024];

__global__ void zero_counts_kernel(int n) {
    int i = blockIdx.x * blockDim.x + threadIdx.x;
    int stride = gridDim.x * blockDim.x;
    for (; i < n; i += stride) g_count[i] = 0;
}

// Vectorized histogram: 4 targets per thread.
__global__ void hist_kernel(const int* __restrict__ acd, int M) {
    int i = blockIdx.x * blockDim.x + threadIdx.x;
    int i4 = i * 4;
    if (i4 + 3 < M) {
        int4 v = *(const int4*)(acd + i4);
        atomicAdd(&g_count[v.x], 1);
        atomicAdd(&g_count[v.y], 1);
        atomicAdd(&g_count[v.z], 1);
        atomicAdd(&g_count[v.w], 1);
    } else {
        for (int k = i4; k < M; k++) atomicAdd(&g_count[k == i4 ? acd[k] : acd[k]], 1);
    }
}

// Pass 1: per-block exclusive scan of counts; block totals to g_blocksums.
__global__ void scan1_kernel(int N) {
    __shared__ int sh[SCAN_T];
    int b = blockIdx.x;
    int t = threadIdx.x;
    int base = b * SCAN_CHUNK + t * SCAN_I;
    int v[SCAN_I];
    int s = 0;
#pragma unroll
    for (int k = 0; k < SCAN_I; k++) {
        int idx = base + k;
        v[k] = (idx < N) ? g_count[idx] : 0;
        s += v[k];
    }
    sh[t] = s;
    __syncthreads();
    for (int off = 1; off < SCAN_T; off <<= 1) {
        int x = (t >= off) ? sh[t - off] : 0;
        __syncthreads();
        sh[t] += x;
        __syncthreads();
    }
    int excl = sh[t] - s;
    if (t == SCAN_T - 1) g_blocksums[b] = sh[SCAN_T - 1];
    int run = excl;
#pragma unroll
    for (int k = 0; k < SCAN_I; k++) {
        int idx = base + k;
        if (idx < N) g_offset[idx] = run;
        run += v[k];
    }
}

// Pass 2: single-block exclusive scan of block sums (nb <= 1024).
__global__ void scan2_kernel(int nb) {
    __shared__ int sh[SCAN_T];
    int t = threadIdx.x;
    int orig = (t < nb) ? g_blocksums[t] : 0;
    sh[t] = orig;
    __syncthreads();
    for (int off = 1; off < SCAN_T; off <<= 1) {
        int x = (t >= off) ? sh[t - off] : 0;
        __syncthreads();
        sh[t] += x;
        __syncthreads();
    }
    if (t < nb) g_blocksums[t] = sh[t] - orig;
}

// Pass 3: add block prefix; initialize cursor.
__global__ void scan3_kernel(int N) {
    int i = blockIdx.x * blockDim.x + threadIdx.x;
    int stride = gridDim.x * blockDim.x;
    for (; i < N; i += stride) {
        int o = g_offset[i] + g_blocksums[i / SCAN_CHUNK];
        g_offset[i] = o;
        g_cursor[i] = o;
    }
}

// Scatter (c,d) directly — hot kernel never touches acd again.
__global__ void scatter_kernel(const int* __restrict__ acd, int M) {
    int i = blockIdx.x * blockDim.x + threadIdx.x;
    if (i < M) {
        int a = acd[i];
        int c = acd[M + i];
        int d = acd[2 * M + i];
        int pos = atomicAdd(&g_cursor[a], 1);
        g_cd[pos] = make_int2(c, d);
    }
}

// One warp per output row. sub=lane>>3 indexes pairs (4-way parallel),
// f=lane&7 indexes float4 features. shfl_xor(8,16) reduction, lanes 0-7 store.
__global__ void __launch_bounds__(256) gather_kernel(
    const float4* __restrict__ A,
    const float4* __restrict__ B,
    float* __restrict__ out,
    int tar)
{
    int warp_id = (blockIdx.x * blockDim.x + threadIdx.x) >> 5;
    if (warp_id >= tar) return;
    int lane = threadIdx.x & 31;
    int sub = lane >> 3;     // 0..3 : which pair slot
    int f = lane & 7;        // 0..7 : which float4 of the row

    int off = __ldg(&g_offset[warp_id]);
    int cnt = __ldg(&g_count[warp_id]);

    float4 acc = make_float4(0.f, 0.f, 0.f, 0.f);
    for (int j = sub; j < cnt; j += 4) {
        int2 cd = __ldg(&g_cd[off + j]);
        float4 av = __ldg(&A[(long long)cd.x * 8 + f]);
        float4 bv = __ldg(&B[(long long)cd.y * 8 + f]);
        acc.x += av.x * bv.x;
        acc.y += av.y * bv.y;
        acc.z += av.z * bv.z;
        acc.w += av.w * bv.w;
    }

    // Reduce the 4 pair-slots (xor bits 3 and 4 keep f invariant).
#pragma unroll
    for (int delta = 8; delta <= 16; delta <<= 1) {
        acc.x += __shfl_xor_sync(0xFFFFFFFFu, acc.x, delta);
        acc.y += __shfl_xor_sync(0xFFFFFFFFu, acc.y, delta);
        acc.z += __shfl_xor_sync(0xFFFFFFFFu, acc.z, delta);
        acc.w += __shfl_xor_sync(0xFFFFFFFFu, acc.w, delta);
    }

    if (lane < 8)
        ((float4*)(out + (long long)warp_id * 32))[f] = acc;
}

extern "C" void kernel_launch(void* const* d_in, const int* in_sizes, int n_in,
                              void* d_out, int out_size) {
    const float4* A = (const float4*)d_in[0];
    const float4* B = (const float4*)d_in[1];
    const int* acd = (const int*)d_in[2];
    float* out = (float*)d_out;

    int M = in_sizes[2] / 3;
    int tar = out_size / 32;
    if (tar > TAR_CAP || M > M_CAP) return;  // capacity guard (never hit)

    int nb_scan = (tar + SCAN_CHUNK - 1) / SCAN_CHUNK;

    zero_counts_kernel<<<1184, 256>>>(tar);
    hist_kernel<<<(M / 4 + 255) / 256, 256>>>(acd, M);
    scan1_kernel<<<nb_scan, SCAN_T>>>(tar);
    scan2_kernel<<<1, SCAN_T>>>(nb_scan);
    scan3_kernel<<<1184, 256>>>(tar);
    scatter_kernel<<<(M + 255) / 256, 256>>>(acd, M);

    long long total_threads = (long long)tar * 32;
    long long blocks = (total_threads + 255) / 256;
    gather_kernel<<<(unsigned)blocks, 256>>>(A, B, out, tar);
}

// round 6
// speedup vs baseline: 1.4652x; 1.4652x over previous
#include <cuda_runtime.h>
#include <cstdint>

// spspmm via counting-sort by target row. Hot gather = 8 threads per output
// row with batched clamped prefetch of up to 4 (c,d) pairs -> all A/B loads
// issued concurrently (one dependency level, high MLP). Output is a single
// coalesced 128B store per row: no atomics, no zero-fill, no RMW read.

#define TAR_CAP 2100000
#define M_CAP   4200000
#define SCAN_T  1024
#define SCAN_I  4
#define SCAN_CHUNK (SCAN_T * SCAN_I)   // 4096

__device__ int  g_count[TAR_CAP];
__device__ int  g_offset[TAR_CAP];
__device__ int  g_cursor[TAR_CAP];
__device__ int2 g_cd[M_CAP];
__device__ int  g_blocksums[1024];

__global__ void zero_counts_kernel(int n) {
    int i = blockIdx.x * blockDim.x + threadIdx.x;
    int stride = gridDim.x * blockDim.x;
    for (; i < n; i += stride) g_count[i] = 0;
}

// Vectorized histogram: 4 targets per thread.
__global__ void hist_kernel(const int* __restrict__ acd, int M) {
    int i = blockIdx.x * blockDim.x + threadIdx.x;
    int i4 = i * 4;
    if (i4 + 3 < M) {
        int4 v = *(const int4*)(acd + i4);
        atomicAdd(&g_count[v.x], 1);
        atomicAdd(&g_count[v.y], 1);
        atomicAdd(&g_count[v.z], 1);
        atomicAdd(&g_count[v.w], 1);
    } else if (i4 < M) {
        for (int k = i4; k < M; k++) atomicAdd(&g_count[acd[k]], 1);
    }
}

// Pass 1: per-block exclusive scan of counts; block totals to g_blocksums.
__global__ void scan1_kernel(int N) {
    __shared__ int sh[SCAN_T];
    int b = blockIdx.x;
    int t = threadIdx.x;
    int base = b * SCAN_CHUNK + t * SCAN_I;
    int v[SCAN_I];
    int s = 0;
#pragma unroll
    for (int k = 0; k < SCAN_I; k++) {
        int idx = base + k;
        v[k] = (idx < N) ? g_count[idx] : 0;
        s += v[k];
    }
    sh[t] = s;
    __syncthreads();
    for (int off = 1; off < SCAN_T; off <<= 1) {
        int x = (t >= off) ? sh[t - off] : 0;
        __syncthreads();
        sh[t] += x;
        __syncthreads();
    }
    int excl = sh[t] - s;
    if (t == SCAN_T - 1) g_blocksums[b] = sh[SCAN_T - 1];
    int run = excl;
#pragma unroll
    for (int k = 0; k < SCAN_I; k++) {
        int idx = base + k;
        if (idx < N) g_offset[idx] = run;
        run += v[k];
    }
}

// Pass 2: single-block exclusive scan of block sums (nb <= 1024).
__global__ void scan2_kernel(int nb) {
    __shared__ int sh[SCAN_T];
    int t = threadIdx.x;
    int orig = (t < nb) ? g_blocksums[t] : 0;
    sh[t] = orig;
    __syncthreads();
    for (int off = 1; off < SCAN_T; off <<= 1) {
        int x = (t >= off) ? sh[t - off] : 0;
        __syncthreads();
        sh[t] += x;
        __syncthreads();
    }
    if (t < nb) g_blocksums[t] = sh[t] - orig;
}

// Pass 3: add block prefix; initialize cursor.
__global__ void scan3_kernel(int N) {
    int i = blockIdx.x * blockDim.x + threadIdx.x;
    int stride = gridDim.x * blockDim.x;
    for (; i < N; i += stride) {
        int o = g_offset[i] + g_blocksums[i / SCAN_CHUNK];
        g_offset[i] = o;
        g_cursor[i] = o;
    }
}

// Scatter (c,d) directly — hot kernel never touches acd again.
__global__ void scatter_kernel(const int* __restrict__ acd, int M) {
    int i = blockIdx.x * blockDim.x + threadIdx.x;
    if (i < M) {
        int a = acd[i];
        int c = acd[M + i];
        int d = acd[2 * M + i];
        int pos = atomicAdd(&g_cursor[a], 1);
        g_cd[pos] = make_int2(c, d);
    }
}

// 8 threads per output row; batched clamped prefetch of 4 pairs for MLP.
__global__ void __launch_bounds__(256) gather_kernel(
    const float4* __restrict__ A,
    const float4* __restrict__ B,
    float* __restrict__ out,
    int tar)
{
    long long gid = (long long)blockIdx.x * blockDim.x + threadIdx.x;
    int r = (int)(gid >> 3);
    int f = (int)(gid & 7);
    if (r >= tar) return;

    int off = __ldg(&g_offset[r]);
    int cnt = __ldg(&g_count[r]);

    float4 acc = make_float4(0.f, 0.f, 0.f, 0.f);

    for (int j = 0; j < cnt; j += 4) {
        int e = cnt - 1;
        // Clamped prefetch: duplicate addresses hit L1; all 4 issue together.
        int2 cd0 = __ldg(&g_cd[off + j]);
        int2 cd1 = __ldg(&g_cd[off + min(j + 1, e)]);
        int2 cd2 = __ldg(&g_cd[off + min(j + 2, e)]);
        int2 cd3 = __ldg(&g_cd[off + min(j + 3, e)]);

        float4 a0 = __ldg(&A[(long long)cd0.x * 8 + f]);
        float4 b0 = __ldg(&B[(long long)cd0.y * 8 + f]);
        float4 a1 = __ldg(&A[(long long)cd1.x * 8 + f]);
        float4 b1 = __ldg(&B[(long long)cd1.y * 8 + f]);
        float4 a2 = __ldg(&A[(long long)cd2.x * 8 + f]);
        float4 b2 = __ldg(&B[(long long)cd2.y * 8 + f]);
        float4 a3 = __ldg(&A[(long long)cd3.x * 8 + f]);
        float4 b3 = __ldg(&B[(long long)cd3.y * 8 + f]);

        acc.x += a0.x * b0.x; acc.y += a0.y * b0.y;
        acc.z += a0.z * b0.z; acc.w += a0.w * b0.w;
        if (j + 1 < cnt) {
            acc.x += a1.x * b1.x; acc.y += a1.y * b1.y;
            acc.z += a1.z * b1.z; acc.w += a1.w * b1.w;
        }
        if (j + 2 < cnt) {
            acc.x += a2.x * b2.x; acc.y += a2.y * b2.y;
            acc.z += a2.z * b2.z; acc.w += a2.w * b2.w;
        }
        if (j + 3 < cnt) {
            acc.x += a3.x * b3.x; acc.y += a3.y * b3.y;
            acc.z += a3.z * b3.z; acc.w += a3.w * b3.w;
        }
    }

    ((float4*)(out + (long long)r * 32))[f] = acc;
}

extern "C" void kernel_launch(void* const* d_in, const int* in_sizes, int n_in,
                              void* d_out, int out_size) {
    const float4* A = (const float4*)d_in[0];
    const float4* B = (const float4*)d_in[1];
    const int* acd = (const int*)d_in[2];
    float* out = (float*)d_out;

    int M = in_sizes[2] / 3;
    int tar = out_size / 32;
    if (tar > TAR_CAP || M > M_CAP) return;  // capacity guard (never hit)

    int nb_scan = (tar + SCAN_CHUNK - 1) / SCAN_CHUNK;

    zero_counts_kernel<<<1184, 256>>>(tar);
    hist_kernel<<<(M / 4 + 256) / 256, 256>>>(acd, M);
    scan1_kernel<<<nb_scan, SCAN_T>>>(tar);
    scan2_kernel<<<1, SCAN_T>>>(nb_scan);
    scan3_kernel<<<1184, 256>>>(tar);
    scatter_kernel<<<(M + 255) / 256, 256>>>(acd, M);

    long long total_threads = (long long)tar * 8;
    long long blocks = (total_threads + 255) / 256;
    gather_kernel<<<(unsigned)blocks, 256>>>(A, B, out, tar);
}

// round 7
// speedup vs baseline: 1.8129x; 1.2373x over previous
#include <cuda_runtime.h>
#include <cstdint>

// spspmm, R2-style atomic kernel + coarse target-bucketing so output atomics
// hit L2-resident zeroed lines:
//   1) block-aggregated scatter of (a,c,d) into 16 coarse buckets by target
//      range (also zeroes output slice 0)
//   2) for each bucket b: pairs kernel (8 thr/pair, red.global.add.v4.f32
//      into the 16MB L2-resident slice) which also pre-zeroes slice b+1.
// Output DRAM traffic: writeback only (256MB) vs zero+fill+wb (768MB) in R2.

#define NB      16
#define CAP     300000          // per-bucket capacity (mean ~262K, sigma ~500)

__device__ int  g_bcursor[NB];
__device__ int  g_a[NB * CAP];
__device__ int2 g_cd[NB * CAP];

__global__ void init_kernel() {
    if (threadIdx.x < NB) g_bcursor[threadIdx.x] = 0;
}

// Block-aggregated bucket scatter + zero output slice 0.
__global__ void __launch_bounds__(256) scatter_kernel(
    const int* __restrict__ acd, int M, int bshift,
    float4* __restrict__ out4, long long z0_end)
{
    __shared__ int s_cnt[NB];
    __shared__ int s_base[NB];
    int i = blockIdx.x * blockDim.x + threadIdx.x;

    if (threadIdx.x < NB) s_cnt[threadIdx.x] = 0;
    __syncthreads();

    int a = 0, c = 0, d = 0, b = 0, p = 0;
    bool valid = (i < M);
    if (valid) {
        a = __ldg(&acd[i]);
        c = __ldg(&acd[M + i]);
        d = __ldg(&acd[2 * M + i]);
        b = a >> bshift;
        p = atomicAdd(&s_cnt[b], 1);
    }
    __syncthreads();
    if (threadIdx.x < NB && s_cnt[threadIdx.x] > 0)
        s_base[threadIdx.x] = atomicAdd(&g_bcursor[threadIdx.x], s_cnt[threadIdx.x]);
    __syncthreads();
    if (valid) {
        int pos = b * CAP + s_base[b] + p;
        g_a[pos] = a;
        g_cd[pos] = make_int2(c, d);
    }

    // Zero slice 0 of the output (grid-stride over float4s).
    float4 z = make_float4(0.f, 0.f, 0.f, 0.f);
    long long stride = (long long)gridDim.x * blockDim.x;
    for (long long j = i; j < z0_end; j += stride) out4[j] = z;
}

// Pairs for bucket b; also zero slice b+1 ([znext0, znext1) in float4 units).
__global__ void __launch_bounds__(256) pairs_kernel(
    const float4* __restrict__ A,
    const float4* __restrict__ B,
    float* __restrict__ out,
    int b, long long znext0, long long znext1)
{
    long long gid = (long long)blockIdx.x * blockDim.x + threadIdx.x;
    long long stride = (long long)gridDim.x * blockDim.x;

    // Pre-zero the NEXT bucket's output slice (disjoint from this bucket's
    // RED targets; ordering vs. its REDs is provided by the kernel boundary).
    {
        float4 z = make_float4(0.f, 0.f, 0.f, 0.f);
        float4* out4 = (float4*)out;
        for (long long j = znext0 + gid; j < znext1; j += stride) out4[j] = z;
    }

    int cnt = g_bcursor[b];          // bucket size (broadcast load)
    int p = (int)(gid >> 3);
    int f = (int)(gid & 7);
    if (p >= cnt) return;

    int base = b * CAP + p;
    int a = __ldg(&g_a[base]);
    int2 cd = __ldg(&g_cd[base]);

    float4 av = __ldg(&A[(long long)cd.x * 8 + f]);
    float4 bv = __ldg(&B[(long long)cd.y * 8 + f]);

    float4 m;
    m.x = av.x * bv.x;
    m.y = av.y * bv.y;
    m.z = av.z * bv.z;
    m.w = av.w * bv.w;

    float* dst = out + (long long)a * 32 + f * 4;
    asm volatile(
        "red.global.add.v4.f32 [%0], {%1, %2, %3, %4};"
        :: "l"(dst), "f"(m.x), "f"(m.y), "f"(m.z), "f"(m.w)
        : "memory");
}

extern "C" void kernel_launch(void* const* d_in, const int* in_sizes, int n_in,
                              void* d_out, int out_size) {
    const float4* A = (const float4*)d_in[0];
    const float4* B = (const float4*)d_in[1];
    const int* acd = (const int*)d_in[2];
    float* out = (float*)d_out;

    int M = in_sizes[2] / 3;
    int tar = out_size / 32;

    // Bucket size = pow2 >= ceil(tar/NB); bucket id = a >> bshift.
    int bsize_min = (tar + NB - 1) / NB;
    int bshift = 0;
    while ((1 << bshift) < bsize_min) bshift++;
    int bsize = 1 << bshift;
    int nb = (tar + bsize - 1) >> bshift;   // <= NB

    init_kernel<<<1, 32>>>();

    // Slice j covers targets [j*bsize, min((j+1)*bsize, tar)) -> float4 range
    // [start*8, end*8).
    long long z0_end = (long long)((bsize < tar) ? bsize : tar) * 8;
    scatter_kernel<<<(M + 255) / 256, 256>>>(acd, M, bshift,
                                             (float4*)d_out, z0_end);

    int pair_blocks = (CAP * 8 + 255) / 256;
    for (int b = 0; b < nb; b++) {
        long long s = (long long)(b + 1) << bshift;
        long long e = (long long)(b + 2) << bshift;
        if (s > tar) s = tar;
        if (e > tar) e = tar;
        long long zn0 = s * 8, zn1 = e * 8;   // empty when b+1 >= nb
        pairs_kernel<<<pair_blocks, 256>>>(A, B, out, b, zn0, zn1);
    }
}

// round 8
// speedup vs baseline: 1.8992x; 1.0476x over previous
#include <cuda_runtime.h>
#include <cstdint>

// spspmm: coarse target-bucketing (8 buckets, 32MB output slices) so the
// scatter atomics land on L2-resident zeroed lines. A/B gathers use __ldcs
// (evict-first) so the ~1GB stream cannot displace the hot slice.
//   1) block-aggregated scatter of (a,c,d) into buckets (+ zero slices 0,1... no: 0)
//   2) per bucket b: pairs kernel (8 thr/pair, red.global.add.v4.f32 into the
//      L2-resident slice), also pre-zeroes slice b+1.
// Output DRAM traffic: final writeback only (256MB) vs zero+fill+wb (768MB).

#define NB      8
#define CAP     560000          // per-bucket capacity (mean ~500K + margin)

__device__ int  g_bcursor[NB];
__device__ int  g_a[NB * CAP];
__device__ int2 g_cd[NB * CAP];

__global__ void init_kernel() {
    if (threadIdx.x < NB) g_bcursor[threadIdx.x] = 0;
}

// Block-aggregated bucket scatter + zero output slice 0.
__global__ void __launch_bounds__(256) scatter_kernel(
    const int* __restrict__ acd, int M, int bshift,
    float4* __restrict__ out4, long long z0_end)
{
    __shared__ int s_cnt[NB];
    __shared__ int s_base[NB];
    int i = blockIdx.x * blockDim.x + threadIdx.x;

    if (threadIdx.x < NB) s_cnt[threadIdx.x] = 0;
    __syncthreads();

    int a = 0, c = 0, d = 0, b = 0, p = 0;
    bool valid = (i < M);
    if (valid) {
        a = __ldcs(&acd[i]);
        c = __ldcs(&acd[M + i]);
        d = __ldcs(&acd[2 * M + i]);
        b = a >> bshift;
        p = atomicAdd(&s_cnt[b], 1);
    }
    __syncthreads();
    if (threadIdx.x < NB && s_cnt[threadIdx.x] > 0)
        s_base[threadIdx.x] = atomicAdd(&g_bcursor[threadIdx.x], s_cnt[threadIdx.x]);
    __syncthreads();
    if (valid) {
        int pos = b * CAP + s_base[b] + p;
        g_a[pos] = a;
        g_cd[pos] = make_int2(c, d);
    }

    // Zero slice 0 of the output (grid-stride over float4s).
    float4 z = make_float4(0.f, 0.f, 0.f, 0.f);
    long long stride = (long long)gridDim.x * blockDim.x;
    for (long long j = i; j < z0_end; j += stride) out4[j] = z;
}

// Pairs for bucket b; also zero slice b+1 ([znext0, znext1) in float4 units).
__global__ void __launch_bounds__(256) pairs_kernel(
    const float4* __restrict__ A,
    const float4* __restrict__ B,
    float* __restrict__ out,
    int b, long long znext0, long long znext1)
{
    long long gid = (long long)blockIdx.x * blockDim.x + threadIdx.x;
    long long stride = (long long)gridDim.x * blockDim.x;

    // Pre-zero the NEXT bucket's output slice (disjoint from this bucket's
    // RED targets; ordering provided by the kernel boundary).
    {
        float4 z = make_float4(0.f, 0.f, 0.f, 0.f);
        float4* out4 = (float4*)out;
        for (long long j = znext0 + gid; j < znext1; j += stride) out4[j] = z;
    }

    int cnt = g_bcursor[b];          // broadcast load
    int p = (int)(gid >> 3);
    int f = (int)(gid & 7);
    if (p >= cnt) return;

    int base = b * CAP + p;
    int a = __ldg(&g_a[base]);
    int2 cd = __ldg(&g_cd[base]);

    // Streaming loads: evict-first, protect the L2-resident output slice.
    float4 av = __ldcs(&A[(long long)cd.x * 8 + f]);
    float4 bv = __ldcs(&B[(long long)cd.y * 8 + f]);

    float4 m;
    m.x = av.x * bv.x;
    m.y = av.y * bv.y;
    m.z = av.z * bv.z;
    m.w = av.w * bv.w;

    float* dst = out + (long long)a * 32 + f * 4;
    asm volatile(
        "red.global.add.v4.f32 [%0], {%1, %2, %3, %4};"
        :: "l"(dst), "f"(m.x), "f"(m.y), "f"(m.z), "f"(m.w)
        : "memory");
}

extern "C" void kernel_launch(void* const* d_in, const int* in_sizes, int n_in,
                              void* d_out, int out_size) {
    const float4* A = (const float4*)d_in[0];
    const float4* B = (const float4*)d_in[1];
    const int* acd = (const int*)d_in[2];
    float* out = (float*)d_out;

    int M = in_sizes[2] / 3;
    int tar = out_size / 32;

    // Bucket size = pow2 >= ceil(tar/NB); bucket id = a >> bshift.
    int bsize_min = (tar + NB - 1) / NB;
    int bshift = 0;
    while ((1 << bshift) < bsize_min) bshift++;
    int bsize = 1 << bshift;
    int nb = (tar + bsize - 1) >> bshift;   // <= NB

    init_kernel<<<1, 32>>>();

    long long z0_end = (long long)((bsize < tar) ? bsize : tar) * 8;
    scatter_kernel<<<(M + 255) / 256, 256>>>(acd, M, bshift,
                                             (float4*)d_out, z0_end);

    int pair_blocks = (CAP * 8 + 255) / 256;
    for (int b = 0; b < nb; b++) {
        long long s = (long long)(b + 1) << bshift;
        long long e = (long long)(b + 2) << bshift;
        if (s > tar) s = tar;
        if (e > tar) e = tar;
        long long zn0 = s * 8, zn1 = e * 8;   // empty when b+1 >= nb
        pairs_kernel<<<pair_blocks, 256>>>(A, B, out, b, zn0, zn1);
    }
}

// round 9
// speedup vs baseline: 2.0413x; 1.0748x over previous
#include <cuda_runtime.h>
#include <cstdint>

// spspmm: coarse target-bucketing (8 buckets, 32MB output slices, L2-resident
// zeroed lines for the scatter atomics) + 4-pairs-per-group gather for MLP=8.
//   1) block-aggregated scatter of (a,c,d) into buckets (+ zero slice 0)
//   2) per bucket b: pairs kernel — each 8-thread group processes 4 pairs:
//      4 broadcast cd loads, 8 concurrent A/B float4 loads (__ldcs evict-first),
//      guarded red.global.add.v4.f32 into the L2-resident slice; also
//      pre-zeroes slice b+1.

#define NB      8
#define CAP     560000          // per-bucket capacity (mean ~500K + margin)

__device__ int  g_bcursor[NB];
__device__ int  g_a[NB * CAP];
__device__ int2 g_cd[NB * CAP];

__global__ void init_kernel() {
    if (threadIdx.x < NB) g_bcursor[threadIdx.x] = 0;
}

// Block-aggregated bucket scatter + zero output slice 0.
__global__ void __launch_bounds__(256) scatter_kernel(
    const int* __restrict__ acd, int M, int bshift,
    float4* __restrict__ out4, long long z0_end)
{
    __shared__ int s_cnt[NB];
    __shared__ int s_base[NB];
    int i = blockIdx.x * blockDim.x + threadIdx.x;

    if (threadIdx.x < NB) s_cnt[threadIdx.x] = 0;
    __syncthreads();

    int a = 0, c = 0, d = 0, b = 0, p = 0;
    bool valid = (i < M);
    if (valid) {
        a = __ldcs(&acd[i]);
        c = __ldcs(&acd[M + i]);
        d = __ldcs(&acd[2 * M + i]);
        b = a >> bshift;
        p = atomicAdd(&s_cnt[b], 1);
    }
    __syncthreads();
    if (threadIdx.x < NB && s_cnt[threadIdx.x] > 0)
        s_base[threadIdx.x] = atomicAdd(&g_bcursor[threadIdx.x], s_cnt[threadIdx.x]);
    __syncthreads();
    if (valid) {
        int pos = b * CAP + s_base[b] + p;
        __stcs(&g_a[pos], a);
        __stcs(&g_cd[pos], make_int2(c, d));
    }

    // Zero slice 0 of the output (grid-stride over float4s); default policy so
    // the zeros stay L2-resident for the first pairs kernel.
    float4 z = make_float4(0.f, 0.f, 0.f, 0.f);
    long long stride = (long long)gridDim.x * blockDim.x;
    for (long long j = i; j < z0_end; j += stride) out4[j] = z;
}

// Pairs for bucket b: 4 pairs per 8-thread group (MLP=8); also zero slice b+1.
__global__ void __launch_bounds__(256) pairs_kernel(
    const float4* __restrict__ A,
    const float4* __restrict__ B,
    float* __restrict__ out,
    int b, long long znext0, long long znext1)
{
    long long gid = (long long)blockIdx.x * blockDim.x + threadIdx.x;
    long long stride = (long long)gridDim.x * blockDim.x;

    // Pre-zero the NEXT bucket's output slice (disjoint from this bucket's
    // RED targets; ordering provided by the kernel boundary).
    {
        float4 z = make_float4(0.f, 0.f, 0.f, 0.f);
        float4* out4 = (float4*)out;
        for (long long j = znext0 + gid; j < znext1; j += stride) out4[j] = z;
    }

    int cnt = g_bcursor[b];          // broadcast load
    int grp = (int)(gid >> 3);
    int f = (int)(gid & 7);
    int p0 = grp * 4;
    if (p0 >= cnt || cnt == 0) return;

    int base = b * CAP + p0;
    int e = cnt - 1 - p0;            // last valid local offset (>=0)

    // 4 broadcast index loads (clamped for the tail group).
    int2 cd0 = __ldg(&g_cd[base]);
    int2 cd1 = __ldg(&g_cd[base + min(1, e)]);
    int2 cd2 = __ldg(&g_cd[base + min(2, e)]);
    int2 cd3 = __ldg(&g_cd[base + min(3, e)]);
    int a0 = __ldg(&g_a[base]);
    int a1 = __ldg(&g_a[base + min(1, e)]);
    int a2 = __ldg(&g_a[base + min(2, e)]);
    int a3 = __ldg(&g_a[base + min(3, e)]);

    // 8 independent streaming gathers in flight.
    float4 av0 = __ldcs(&A[(long long)cd0.x * 8 + f]);
    float4 bv0 = __ldcs(&B[(long long)cd0.y * 8 + f]);
    float4 av1 = __ldcs(&A[(long long)cd1.x * 8 + f]);
    float4 bv1 = __ldcs(&B[(long long)cd1.y * 8 + f]);
    float4 av2 = __ldcs(&A[(long long)cd2.x * 8 + f]);
    float4 bv2 = __ldcs(&B[(long long)cd2.y * 8 + f]);
    float4 av3 = __ldcs(&A[(long long)cd3.x * 8 + f]);
    float4 bv3 = __ldcs(&B[(long long)cd3.y * 8 + f]);

    float4 m;
    m.x = av0.x * bv0.x; m.y = av0.y * bv0.y;
    m.z = av0.z * bv0.z; m.w = av0.w * bv0.w;
    {
        float* dst = out + (long long)a0 * 32 + f * 4;
        asm volatile("red.global.add.v4.f32 [%0], {%1, %2, %3, %4};"
                     :: "l"(dst), "f"(m.x), "f"(m.y), "f"(m.z), "f"(m.w) : "memory");
    }
    if (e >= 1) {
        m.x = av1.x * bv1.x; m.y = av1.y * bv1.y;
        m.z = av1.z * bv1.z; m.w = av1.w * bv1.w;
        float* dst = out + (long long)a1 * 32 + f * 4;
        asm volatile("red.global.add.v4.f32 [%0], {%1, %2, %3, %4};"
                     :: "l"(dst), "f"(m.x), "f"(m.y), "f"(m.z), "f"(m.w) : "memory");
    }
    if (e >= 2) {
        m.x = av2.x * bv2.x; m.y = av2.y * bv2.y;
        m.z = av2.z * bv2.z; m.w = av2.w * bv2.w;
        float* dst = out + (long long)a2 * 32 + f * 4;
        asm volatile("red.global.add.v4.f32 [%0], {%1, %2, %3, %4};"
                     :: "l"(dst), "f"(m.x), "f"(m.y), "f"(m.z), "f"(m.w) : "memory");
    }
    if (e >= 3) {
        m.x = av3.x * bv3.x; m.y = av3.y * bv3.y;
        m.z = av3.z * bv3.z; m.w = av3.w * bv3.w;
        float* dst = out + (long long)a3 * 32 + f * 4;
        asm volatile("red.global.add.v4.f32 [%0], {%1, %2, %3, %4};"
                     :: "l"(dst), "f"(m.x), "f"(m.y), "f"(m.z), "f"(m.w) : "memory");
    }
}

extern "C" void kernel_launch(void* const* d_in, const int* in_sizes, int n_in,
                              void* d_out, int out_size) {
    const float4* A = (const float4*)d_in[0];
    const float4* B = (const float4*)d_in[1];
    const int* acd = (const int*)d_in[2];
    float* out = (float*)d_out;

    int M = in_sizes[2] / 3;
    int tar = out_size / 32;

    // Bucket size = pow2 >= ceil(tar/NB); bucket id = a >> bshift.
    int bsize_min = (tar + NB - 1) / NB;
    int bshift = 0;
    while ((1 << bshift) < bsize_min) bshift++;
    int bsize = 1 << bshift;
    int nb = (tar + bsize - 1) >> bshift;   // <= NB

    init_kernel<<<1, 32>>>();

    long long z0_end = (long long)((bsize < tar) ? bsize : tar) * 8;
    scatter_kernel<<<(M + 255) / 256, 256>>>(acd, M, bshift,
                                             (float4*)d_out, z0_end);

    // 4 pairs per 8-thread group -> 2 threads per pair slot.
    int pair_blocks = ((CAP + 3) / 4 * 8 + 255) / 256;
    for (int b = 0; b < nb; b++) {
        long long s = (long long)(b + 1) << bshift;
        long long e = (long long)(b + 2) << bshift;
        if (s > tar) s = tar;
        if (e > tar) e = tar;
        long long zn0 = s * 8, zn1 = e * 8;   // empty when b+1 >= nb
        pairs_kernel<<<pair_blocks, 256>>>(A, B, out, b, zn0, zn1);
    }
}

// round 10
// speedup vs baseline: 2.1035x; 1.0305x over previous
#include <cuda_runtime.h>
#include <cstdint>

// spspmm: coarse target-bucketing (8 buckets, 32MB L2-resident output slices)
// + packed-int4 indices + 2-pairs-per-group gather.
//   1) block-aggregated scatter of packed (a,c,d,0) int4 into buckets
//      (+ zero output slice 0)
//   2) per bucket b: pairs kernel — each 8-thread group processes 2 pairs:
//      2 broadcast int4 index loads, 4 concurrent A/B float4 __ldcs gathers,
//      guarded red.global.add.v4.f32 into the L2-resident slice; also
//      pre-zeroes slice b+1.
// Output DRAM traffic: final writeback only (256MB) vs zero+fill+wb (768MB).

#define NB      8
#define CAP     560000          // per-bucket capacity (expected max ~524K + 36K)

__device__ int  g_bcursor[NB];
__device__ int4 g_pk[NB * CAP];   // (a, c, d, unused)

__global__ void init_kernel() {
    if (threadIdx.x < NB) g_bcursor[threadIdx.x] = 0;
}

// Block-aggregated bucket scatter + zero output slice 0.
__global__ void __launch_bounds__(256) scatter_kernel(
    const int* __restrict__ acd, int M, int bshift,
    float4* __restrict__ out4, long long z0_end)
{
    __shared__ int s_cnt[NB];
    __shared__ int s_base[NB];
    int i = blockIdx.x * blockDim.x + threadIdx.x;

    if (threadIdx.x < NB) s_cnt[threadIdx.x] = 0;
    __syncthreads();

    int a = 0, c = 0, d = 0, b = 0, p = 0;
    bool valid = (i < M);
    if (valid) {
        a = __ldcs(&acd[i]);
        c = __ldcs(&acd[M + i]);
        d = __ldcs(&acd[2 * M + i]);
        b = a >> bshift;
        p = atomicAdd(&s_cnt[b], 1);
    }
    __syncthreads();
    if (threadIdx.x < NB && s_cnt[threadIdx.x] > 0)
        s_base[threadIdx.x] = atomicAdd(&g_bcursor[threadIdx.x], s_cnt[threadIdx.x]);
    __syncthreads();
    if (valid) {
        int pos = b * CAP + s_base[b] + p;
        __stcs(&g_pk[pos], make_int4(a, c, d, 0));
    }

    // Zero slice 0 (grid-stride, default policy -> stays L2-resident).
    float4 z = make_float4(0.f, 0.f, 0.f, 0.f);
    long long stride = (long long)gridDim.x * blockDim.x;
    for (long long j = i; j < z0_end; j += stride) out4[j] = z;
}

// Pairs for bucket b: 2 pairs per 8-thread group; also zero slice b+1.
__global__ void __launch_bounds__(256) pairs_kernel(
    const float4* __restrict__ A,
    const float4* __restrict__ B,
    float* __restrict__ out,
    int b, long long znext0, long long znext1)
{
    long long gid = (long long)blockIdx.x * blockDim.x + threadIdx.x;
    long long stride = (long long)gridDim.x * blockDim.x;

    // Pre-zero the NEXT bucket's output slice (disjoint from this bucket's
    // RED targets; ordering provided by the kernel boundary).
    {
        float4 z = make_float4(0.f, 0.f, 0.f, 0.f);
        float4* out4 = (float4*)out;
        for (long long j = znext0 + gid; j < znext1; j += stride) out4[j] = z;
    }

    int cnt = g_bcursor[b];          // broadcast load
    int grp = (int)(gid >> 3);
    int f = (int)(gid & 7);
    int p0 = grp * 2;
    if (p0 >= cnt) return;

    int base = b * CAP + p0;
    int e = cnt - 1 - p0;            // last valid local offset (>= 0)

    // 2 broadcast packed index loads (clamped tail).
    int4 k0 = __ldg(&g_pk[base]);
    int4 k1 = __ldg(&g_pk[base + min(1, e)]);

    // 4 independent streaming gathers in flight.
    float4 av0 = __ldcs(&A[(long long)k0.y * 8 + f]);
    float4 bv0 = __ldcs(&B[(long long)k0.z * 8 + f]);
    float4 av1 = __ldcs(&A[(long long)k1.y * 8 + f]);
    float4 bv1 = __ldcs(&B[(long long)k1.z * 8 + f]);

    float4 m;
    m.x = av0.x * bv0.x; m.y = av0.y * bv0.y;
    m.z = av0.z * bv0.z; m.w = av0.w * bv0.w;
    {
        float* dst = out + (long long)k0.x * 32 + f * 4;
        asm volatile("red.global.add.v4.f32 [%0], {%1, %2, %3, %4};"
                     :: "l"(dst), "f"(m.x), "f"(m.y), "f"(m.z), "f"(m.w) : "memory");
    }
    if (e >= 1) {
        m.x = av1.x * bv1.x; m.y = av1.y * bv1.y;
        m.z = av1.z * bv1.z; m.w = av1.w * bv1.w;
        float* dst = out + (long long)k1.x * 32 + f * 4;
        asm volatile("red.global.add.v4.f32 [%0], {%1, %2, %3, %4};"
                     :: "l"(dst), "f"(m.x), "f"(m.y), "f"(m.z), "f"(m.w) : "memory");
    }
}

extern "C" void kernel_launch(void* const* d_in, const int* in_sizes, int n_in,
                              void* d_out, int out_size) {
    const float4* A = (const float4*)d_in[0];
    const float4* B = (const float4*)d_in[1];
    const int* acd = (const int*)d_in[2];
    float* out = (float*)d_out;

    int M = in_sizes[2] / 3;
    int tar = out_size / 32;

    // Bucket size = pow2 >= ceil(tar/NB); bucket id = a >> bshift.
    int bsize_min = (tar + NB - 1) / NB;
    int bshift = 0;
    while ((1 << bshift) < bsize_min) bshift++;
    int bsize = 1 << bshift;
    int nb = (tar + bsize - 1) >> bshift;   // <= NB

    init_kernel<<<1, 32>>>();

    long long z0_end = (long long)((bsize < tar) ? bsize : tar) * 8;
    scatter_kernel<<<(M + 255) / 256, 256>>>(acd, M, bshift,
                                             (float4*)d_out, z0_end);

    // 2 pairs per 8-thread group.
    int pair_blocks = ((CAP + 1) / 2 * 8 + 255) / 256;
    for (int b = 0; b < nb; b++) {
        long long s = (long long)(b + 1) << bshift;
        long long e = (long long)(b + 2) << bshift;
        if (s > tar) s = tar;
        if (e > tar) e = tar;
        long long zn0 = s * 8, zn1 = e * 8;   // empty when b+1 >= nb
        pairs_kernel<<<pair_blocks, 256>>>(A, B, out, b, zn0, zn1);
    }
}